// round 16
// baseline (speedup 1.0000x reference)
#include <cuda_runtime.h>
#include <cuda_bf16.h>
#include <cstdint>

// ---------------------------------------------------------------------------
// PrecondWL: out[node] = sum over node's pins of clamp(w[net],1)/(deg[net]-1)
// (deg>1 only), movable nodes only.
//
// Phase 1: cnet[n] = deg>1 ? max(w,1)/(deg-1) : 0   (streaming, vec4)
// Phase 0: fixed-node zeros
// Barrier: sense-reversing, replay-safe
// Phase 2: chunked. cp.async.bulk (TMA engine) stages pins+starts for 1024
//          nodes into smem (double-buffered, 1-ahead pipeline) so the L1tex
//          wavefront queue carries ONLY the 16M random 4B gathers + stores.
//          Exact uniformity check (s==4i) per node from smem; non-matching
//          nodes use a fully-global generic CSR walk. Tail via global loop.
// Floor: 16M random gathers ~= 108K wf-cyc/SM; prior best ran ~100% incl.
// coalesced overhead — this round removes that overhead from L1tex.
// ---------------------------------------------------------------------------

#define N_NETS_MAX 2000000
__device__ float    g_cnet[N_NETS_MAX + 4];
__device__ unsigned g_bar_count = 0;
__device__ unsigned g_bar_sense = 0;

#define C_NODES   1024
#define PIN_BYTES (C_NODES * 4 * 4)   // 16384
#define ST_BYTES  (C_NODES * 4)       // 4096 (starts[i0..i0+1023]); +1 via scalar
#define TX_BYTES  (PIN_BYTES + ST_BYTES)

__device__ __forceinline__ uint32_t smem_u32(const void* p) {
    uint32_t a;
    asm("{ .reg .u64 t; cvta.to.shared.u64 t, %1; cvt.u32.u64 %0, t; }"
        : "=r"(a) : "l"(p));
    return a;
}

__device__ __forceinline__ void mbar_init(uint32_t mbar, uint32_t count) {
    asm volatile("mbarrier.init.shared.b64 [%0], %1;" :: "r"(mbar), "r"(count) : "memory");
}
__device__ __forceinline__ void mbar_expect_tx(uint32_t mbar, uint32_t bytes) {
    asm volatile("mbarrier.arrive.expect_tx.shared.b64 _, [%0], %1;"
                 :: "r"(mbar), "r"(bytes) : "memory");
}
__device__ __forceinline__ void mbar_wait(uint32_t mbar, uint32_t parity) {
    uint32_t done;
    asm volatile(
        "{\n\t.reg .pred p;\n\t"
        "mbarrier.try_wait.parity.acquire.cta.shared::cta.b64 p, [%1], %2;\n\t"
        "selp.b32 %0, 1, 0, p;\n\t}"
        : "=r"(done) : "r"(mbar), "r"(parity) : "memory");
    if (!done) {
        asm volatile(
            "{\n\t.reg .pred P1;\n\t"
            "WL_%=:\n\t"
            "mbarrier.try_wait.parity.acquire.cta.shared::cta.b64 P1, [%0], %1, 0x989680;\n\t"
            "@P1 bra.uni WD_%=;\n\t"
            "bra.uni WL_%=;\n\t"
            "WD_%=:\n\t}"
            :: "r"(mbar), "r"(parity) : "memory");
    }
}
__device__ __forceinline__ void bulk_g2s(uint32_t dst_smem, const void* gsrc,
                                         uint32_t bytes, uint32_t mbar) {
    asm volatile(
        "cp.async.bulk.shared::cta.global.mbarrier::complete_tx::bytes [%0], [%1], %2, [%3];"
        :: "r"(dst_smem), "l"(gsrc), "r"(bytes), "r"(mbar) : "memory");
}

__device__ __forceinline__ float node_generic(const int* __restrict__ n2p,
                                              const int* __restrict__ pin2net,
                                              int s, int e) {
    float r = 0.0f;
    for (int j = s; j < e; ++j) {
        int p = __ldcs(n2p + j);
        int n = __ldcg(pin2net + p);
        r += __ldg(g_cnet + n);
    }
    return r;
}

__global__ void __launch_bounds__(256)
precond_fused_kernel(const float* __restrict__ net_weights,
                     const int*   __restrict__ net2pin,      // starts, n_nets+1
                     const int*   __restrict__ n2p_start,    // starts, num_nodes+1
                     const int*   __restrict__ n2p,          // node->pin flat (perm)
                     const int*   __restrict__ pin2net,
                     const int*   __restrict__ movable_ptr,  // may be null
                     int movable_const,
                     float* __restrict__ out,
                     int n_nets, int num_nodes, int nblocks)
{
    __shared__ alignas(16) int sh_pins[2][C_NODES * 4];
    __shared__ alignas(16) int sh_starts[2][C_NODES + 4];   // [C_NODES] = boundary
    __shared__ alignas(8)  unsigned long long sh_mbar[2];

    const int tid      = blockIdx.x * blockDim.x + threadIdx.x;
    const int nthreads = nblocks * blockDim.x;
    const int movable  = movable_ptr ? __ldg(movable_ptr) : movable_const;

    // mbarrier init fresh each launch (replay-safe)
    if (threadIdx.x == 0) {
        mbar_init(smem_u32(&sh_mbar[0]), 1);
        mbar_init(smem_u32(&sh_mbar[1]), 1);
    }

    // ---------------- Phase 1: per-net contribution (vectorized x4) --------
    const int nq = n_nets >> 2;
    for (int q = tid; q < nq; q += nthreads) {
        int4   s4  = __ldcs(reinterpret_cast<const int4*>(net2pin) + q);
        int    s4e = __ldcs(net2pin + 4 * q + 4);
        float4 w4  = __ldcs(reinterpret_cast<const float4*>(net_weights) + q);
        int d0 = s4.y - s4.x;
        int d1 = s4.z - s4.y;
        int d2 = s4.w - s4.z;
        int d3 = s4e  - s4.w;
        float4 c;
        c.x = (d0 > 1) ? fmaxf(w4.x, 1.0f) / (float)(d0 - 1) : 0.0f;
        c.y = (d1 > 1) ? fmaxf(w4.y, 1.0f) / (float)(d1 - 1) : 0.0f;
        c.z = (d2 > 1) ? fmaxf(w4.z, 1.0f) / (float)(d2 - 1) : 0.0f;
        c.w = (d3 > 1) ? fmaxf(w4.w, 1.0f) / (float)(d3 - 1) : 0.0f;
        *(reinterpret_cast<float4*>(g_cnet) + q) = c;
    }
    for (int n = (nq << 2) + tid; n < n_nets; n += nthreads) {  // generic tail
        int s = __ldcs(net2pin + n);
        int e = __ldcs(net2pin + n + 1);
        int d = e - s;
        float w = fmaxf(__ldcs(net_weights + n), 1.0f);
        g_cnet[n] = (d > 1) ? (w / (float)(d - 1)) : 0.0f;
    }

    // ---------------- Phase 0: fixed-node zeros ----------------------------
    for (int i = movable + tid; i < num_nodes; i += nthreads)
        __stcs(out + i, 0.0f);

    // ---------------- Grid barrier (sense-reversing, replay-safe) ----------
    __syncthreads();   // also orders mbar_init before any bulk copy use
    if (threadIdx.x == 0) {
        __threadfence();
        unsigned oldsense = *((volatile unsigned*)&g_bar_sense);
        unsigned arrived  = atomicAdd(&g_bar_count, 1u);
        if (arrived == (unsigned)nblocks - 1u) {
            g_bar_count = 0;
            __threadfence();
            *((volatile unsigned*)&g_bar_sense) = oldsense ^ 1u;
        } else {
            while (*((volatile unsigned*)&g_bar_sense) == oldsense) {
                __nanosleep(64);
            }
        }
        __threadfence();
    }
    __syncthreads();

    // ---------------- Phase 2: chunked gather (TMA-staged operands) --------
    const int nchunks = movable / C_NODES;   // full chunks
    int phase[2] = {0, 0};
    int buf = 0;

    // Prefetch first chunk for this block.
    int c0 = blockIdx.x;
    if (threadIdx.x == 0 && c0 < nchunks) {
        int i0 = c0 * C_NODES;
        uint32_t mb = smem_u32(&sh_mbar[0]);
        mbar_expect_tx(mb, TX_BYTES);
        bulk_g2s(smem_u32(&sh_pins[0][0]),   n2p + 4 * i0,  PIN_BYTES, mb);
        bulk_g2s(smem_u32(&sh_starts[0][0]), n2p_start + i0, ST_BYTES,  mb);
        sh_starts[0][C_NODES] = __ldg(n2p_start + i0 + C_NODES);  // boundary
    }

    for (int c = c0; c < nchunks; c += nblocks) {
        const int nb = buf ^ 1;
        __syncthreads();   // prior processing of buffer nb is complete
        if (threadIdx.x == 0 && (c + nblocks) < nchunks) {
            int i0n = (c + nblocks) * C_NODES;
            uint32_t mb = smem_u32(&sh_mbar[nb]);
            mbar_expect_tx(mb, TX_BYTES);
            bulk_g2s(smem_u32(&sh_pins[nb][0]),   n2p + 4 * i0n,  PIN_BYTES, mb);
            bulk_g2s(smem_u32(&sh_starts[nb][0]), n2p_start + i0n, ST_BYTES,  mb);
            sh_starts[nb][C_NODES] = __ldg(n2p_start + i0n + C_NODES);
        }
        // Wait for current buffer's data.
        mbar_wait(smem_u32(&sh_mbar[buf]), (uint32_t)phase[buf]);
        phase[buf] ^= 1;
        __syncthreads();   // boundary scalar store visible to all

        const int i0 = c * C_NODES;
        #pragma unroll
        for (int k = 0; k < C_NODES / 256; ++k) {
            const int tpos = threadIdx.x + (k << 8);
            const int i = i0 + tpos;
            const int s = sh_starts[buf][tpos];
            const int e = sh_starts[buf][tpos + 1];
            float r;
            if ((s == 4 * i) & (e == s + 4)) {
                // Pins live in this chunk's smem at 4*tpos (conflict-free LDS128).
                int4 p = *reinterpret_cast<const int4*>(&sh_pins[buf][4 * tpos]);
                int a = __ldcg(pin2net + p.x);
                int b = __ldcg(pin2net + p.y);
                int c2 = __ldcg(pin2net + p.z);
                int d = __ldcg(pin2net + p.w);
                r = (__ldg(g_cnet + a) + __ldg(g_cnet + b)) +
                    (__ldg(g_cnet + c2) + __ldg(g_cnet + d));
            } else {
                r = node_generic(n2p, pin2net, s, e);   // fully-global fallback
            }
            __stcs(out + i, r);
        }
        buf = nb;
    }

    // Tail nodes (movable % C_NODES), plain global path.
    for (int i = nchunks * C_NODES + tid; i < movable; i += nthreads) {
        int s = __ldcs(n2p_start + i);
        int e = __ldcs(n2p_start + i + 1);
        __stcs(out + i, node_generic(n2p, pin2net, s, e));
    }
}

extern "C" void kernel_launch(void* const* d_in, const int* in_sizes, int n_in,
                              void* d_out, int out_size) {
    // metadata order:
    // 0: net_weights         f32 [N_NETS]
    // 1: flat_node2pin_start i32 [N_NODES+1]
    // 2: flat_node2pin       i32 [N_PINS]
    // 3: pin2net_map         i32 [N_PINS]
    // 4: flat_net2pin        i32 [N_NETS+1]
    // 5: num_movable_nodes   scalar buffer (if present)
    const float* net_weights = (const float*)d_in[0];
    const int*   n2p_start   = (const int*)d_in[1];
    const int*   n2p         = (const int*)d_in[2];
    const int*   pin2net     = (const int*)d_in[3];
    const int*   net2pin     = (const int*)d_in[4];
    const int*   movable_ptr = (n_in >= 6) ? (const int*)d_in[5] : nullptr;

    int n_nets    = in_sizes[4] - 1;
    int num_nodes = in_sizes[1] - 1;
    if (n_nets > N_NETS_MAX) n_nets = N_NETS_MAX;

    const int TPB = 256;

    // Exact-residency grid so the device barrier cannot deadlock
    // (occupancy API accounts for the 41KB static smem).
    int dev = 0;
    cudaGetDevice(&dev);
    int sms = 148;
    cudaDeviceGetAttribute(&sms, cudaDevAttrMultiProcessorCount, dev);
    int bpm = 1;
    cudaOccupancyMaxActiveBlocksPerMultiprocessor(&bpm, precond_fused_kernel, TPB, 0);
    if (bpm < 1) bpm = 1;
    int grid = sms * bpm;

    precond_fused_kernel<<<grid, TPB>>>(
        net_weights, net2pin, n2p_start, n2p, pin2net,
        movable_ptr, 1800000, (float*)d_out,
        n_nets, num_nodes, grid);
}

// round 17
// speedup vs baseline: 1.9401x; 1.9401x over previous
#include <cuda_runtime.h>
#include <cuda_bf16.h>

// ---------------------------------------------------------------------------
// PrecondWL: out[node] = sum over node's pins of clamp(w[net],1)/(deg[net]-1)
// (deg>1 only), movable nodes only.
//
// Design = R7 best config (64.0us) + phase-1 overlap:
//   Pre-barrier: each thread issues pin2net gathers for its first 2 nodes and
//     stashes the 8 net ids in registers (no dependence on cnet; results not
//     consumed until post-barrier -> latency hidden under phase 1 + barrier).
//   Phase 1: cnet[n] = deg>1 ? max(w,1)/(deg-1) : 0   (streaming, vec4)
//   Phase 0: fixed-node zeros
//   Barrier: sense-reversing, replay-safe
//   Phase 2: finish stashed nodes (cnet gathers only), then the proven
//     single-node grid-stride loop for the rest.
// Floor: 16M random 4B gathers ~= 108K wf-cyc/SM; this removes the ~3us of
// serialized phase-1 time where the gather pipe idled.
// ---------------------------------------------------------------------------

#define N_NETS_MAX 2000000
__device__ float    g_cnet[N_NETS_MAX + 4];
__device__ unsigned g_bar_count = 0;
__device__ unsigned g_bar_sense = 0;

__device__ __forceinline__ float node_generic(const int* __restrict__ n2p,
                                              const int* __restrict__ pin2net,
                                              int s, int e) {
    float r = 0.0f;
    for (int j = s; j < e; ++j) {
        int p = __ldcs(n2p + j);
        int n = __ldcg(pin2net + p);
        r += __ldg(g_cnet + n);
    }
    return r;
}

__global__ void __launch_bounds__(256)
precond_fused_kernel(const float* __restrict__ net_weights,
                     const int*   __restrict__ net2pin,      // starts, n_nets+1
                     const int*   __restrict__ n2p_start,    // starts, num_nodes+1
                     const int*   __restrict__ n2p,          // node->pin flat (perm)
                     const int*   __restrict__ pin2net,
                     const int*   __restrict__ movable_ptr,  // may be null
                     int movable_const,
                     float* __restrict__ out,
                     int n_nets, int num_nodes, int nblocks)
{
    const int tid      = blockIdx.x * blockDim.x + threadIdx.x;
    const int nthreads = nblocks * blockDim.x;
    const int movable  = movable_ptr ? __ldg(movable_ptr) : movable_const;

    // -------- Pre-barrier stash: pin2net gathers for first 2 nodes ---------
    // stash[k].x == -1  => node needs generic path post-barrier.
    int4 stash0 = make_int4(-1, 0, 0, 0);
    int4 stash1 = make_int4(-1, 0, 0, 0);
    {
        const int i0 = tid;
        if (i0 < movable) {
            int s = __ldcs(n2p_start + i0);
            int e = __ldcs(n2p_start + i0 + 1);
            if ((e - s) == 4 && (s & 3) == 0) {
                int4 p = __ldcs(reinterpret_cast<const int4*>(n2p + s));
                stash0.x = __ldcg(pin2net + p.x);
                stash0.y = __ldcg(pin2net + p.y);
                stash0.z = __ldcg(pin2net + p.z);
                stash0.w = __ldcg(pin2net + p.w);
            }
        }
        const int i1 = tid + nthreads;
        if (i1 < movable) {
            int s = __ldcs(n2p_start + i1);
            int e = __ldcs(n2p_start + i1 + 1);
            if ((e - s) == 4 && (s & 3) == 0) {
                int4 p = __ldcs(reinterpret_cast<const int4*>(n2p + s));
                stash1.x = __ldcg(pin2net + p.x);
                stash1.y = __ldcg(pin2net + p.y);
                stash1.z = __ldcg(pin2net + p.z);
                stash1.w = __ldcg(pin2net + p.w);
            }
        }
    }

    // ---------------- Phase 1: per-net contribution (vectorized x4) --------
    const int nq = n_nets >> 2;
    for (int q = tid; q < nq; q += nthreads) {
        int4   s4  = __ldcs(reinterpret_cast<const int4*>(net2pin) + q);
        int    s4e = __ldcs(net2pin + 4 * q + 4);
        float4 w4  = __ldcs(reinterpret_cast<const float4*>(net_weights) + q);
        int d0 = s4.y - s4.x;
        int d1 = s4.z - s4.y;
        int d2 = s4.w - s4.z;
        int d3 = s4e  - s4.w;
        float4 c;
        c.x = (d0 > 1) ? fmaxf(w4.x, 1.0f) / (float)(d0 - 1) : 0.0f;
        c.y = (d1 > 1) ? fmaxf(w4.y, 1.0f) / (float)(d1 - 1) : 0.0f;
        c.z = (d2 > 1) ? fmaxf(w4.z, 1.0f) / (float)(d2 - 1) : 0.0f;
        c.w = (d3 > 1) ? fmaxf(w4.w, 1.0f) / (float)(d3 - 1) : 0.0f;
        *(reinterpret_cast<float4*>(g_cnet) + q) = c;   // default: keep in L2
    }
    for (int n = (nq << 2) + tid; n < n_nets; n += nthreads) {  // generic tail
        int s = __ldcs(net2pin + n);
        int e = __ldcs(net2pin + n + 1);
        int d = e - s;
        float w = fmaxf(__ldcs(net_weights + n), 1.0f);
        g_cnet[n] = (d > 1) ? (w / (float)(d - 1)) : 0.0f;
    }

    // ---------------- Phase 0: fixed-node zeros ----------------------------
    for (int i = movable + tid; i < num_nodes; i += nthreads)
        __stcs(out + i, 0.0f);

    // ---------------- Grid barrier (sense-reversing, replay-safe) ----------
    __syncthreads();
    if (threadIdx.x == 0) {
        __threadfence();  // publish this block's cnet writes
        unsigned oldsense = *((volatile unsigned*)&g_bar_sense);
        unsigned arrived  = atomicAdd(&g_bar_count, 1u);
        if (arrived == (unsigned)nblocks - 1u) {
            g_bar_count = 0;                      // reset for next replay
            __threadfence();
            *((volatile unsigned*)&g_bar_sense) = oldsense ^ 1u;  // release
        } else {
            while (*((volatile unsigned*)&g_bar_sense) == oldsense) {
                __nanosleep(64);
            }
        }
        __threadfence();  // acquire
    }
    __syncthreads();

    // ---------------- Phase 2a: finish the 2 stashed nodes -----------------
    if (tid < movable) {
        float r;
        if (stash0.x >= 0) {
            r = (__ldg(g_cnet + stash0.x) + __ldg(g_cnet + stash0.y)) +
                (__ldg(g_cnet + stash0.z) + __ldg(g_cnet + stash0.w));
        } else {
            int s = __ldcs(n2p_start + tid);
            int e = __ldcs(n2p_start + tid + 1);
            r = node_generic(n2p, pin2net, s, e);
        }
        __stcs(out + tid, r);
    }
    if (tid + nthreads < movable) {
        const int i1 = tid + nthreads;
        float r;
        if (stash1.x >= 0) {
            r = (__ldg(g_cnet + stash1.x) + __ldg(g_cnet + stash1.y)) +
                (__ldg(g_cnet + stash1.z) + __ldg(g_cnet + stash1.w));
        } else {
            int s = __ldcs(n2p_start + i1);
            int e = __ldcs(n2p_start + i1 + 1);
            r = node_generic(n2p, pin2net, s, e);
        }
        __stcs(out + i1, r);
    }

    // ---------------- Phase 2b: remaining nodes (proven loop) --------------
    for (int i = tid + 2 * nthreads; i < movable; i += nthreads) {
        int s, e;
        if ((i & 1) == 0) {
            int2 se = __ldcs(reinterpret_cast<const int2*>(n2p_start + i));
            s = se.x; e = se.y;
        } else {
            s = __ldcs(n2p_start + i);
            e = __ldcs(n2p_start + i + 1);
        }
        float r;
        if ((e - s) == 4 && (s & 3) == 0) {
            int4 p = __ldcs(reinterpret_cast<const int4*>(n2p + s));
            int a = __ldcg(pin2net + p.x);
            int b = __ldcg(pin2net + p.y);
            int c = __ldcg(pin2net + p.z);
            int d = __ldcg(pin2net + p.w);
            r = (__ldg(g_cnet + a) + __ldg(g_cnet + b)) +
                (__ldg(g_cnet + c) + __ldg(g_cnet + d));
        } else {
            r = node_generic(n2p, pin2net, s, e);
        }
        __stcs(out + i, r);
    }
}

extern "C" void kernel_launch(void* const* d_in, const int* in_sizes, int n_in,
                              void* d_out, int out_size) {
    // metadata order:
    // 0: net_weights         f32 [N_NETS]
    // 1: flat_node2pin_start i32 [N_NODES+1]
    // 2: flat_node2pin       i32 [N_PINS]
    // 3: pin2net_map         i32 [N_PINS]
    // 4: flat_net2pin        i32 [N_NETS+1]
    // 5: num_movable_nodes   scalar buffer (if present)
    const float* net_weights = (const float*)d_in[0];
    const int*   n2p_start   = (const int*)d_in[1];
    const int*   n2p         = (const int*)d_in[2];
    const int*   pin2net     = (const int*)d_in[3];
    const int*   net2pin     = (const int*)d_in[4];
    const int*   movable_ptr = (n_in >= 6) ? (const int*)d_in[5] : nullptr;

    int n_nets    = in_sizes[4] - 1;
    int num_nodes = in_sizes[1] - 1;
    if (n_nets > N_NETS_MAX) n_nets = N_NETS_MAX;

    const int TPB = 256;

    // Exact-residency grid so the device barrier cannot deadlock.
    int dev = 0;
    cudaGetDevice(&dev);
    int sms = 148;
    cudaDeviceGetAttribute(&sms, cudaDevAttrMultiProcessorCount, dev);
    int bpm = 1;
    cudaOccupancyMaxActiveBlocksPerMultiprocessor(&bpm, precond_fused_kernel, TPB, 0);
    if (bpm < 1) bpm = 1;
    int grid = sms * bpm;

    precond_fused_kernel<<<grid, TPB>>>(
        net_weights, net2pin, n2p_start, n2p, pin2net,
        movable_ptr, 1800000, (float*)d_out,
        n_nets, num_nodes, grid);
}